// round 17
// baseline (speedup 1.0000x reference)
#include <cuda_runtime.h>
#include <cuda_fp16.h>
#include <cstdint>

#define BATCH  32
#define SMAX   222
#define S1     197
#define DMODEL 768
#define NLAYER 12
#define NHEAD  12
#define HDIM   64
#define MLPD   3072
#define POOL   10
#define SEL    5
#define PLEN   5
#define NCLS   100
#define PSTRIDE 224

// ---------------- scratch (static device allocations; harness-legal) ----------------
__device__ float  g_x   [BATCH * SMAX * DMODEL];
__device__ float  g_x0  [BATCH * S1   * DMODEL];
__device__ float  g_h   [BATCH * SMAX * DMODEL];     // final-LN output (fp32)
__device__ __half g_hh  [BATCH * SMAX * DMODEL];     // in-layer LN output (half)
__device__ __half g_qkvh[BATCH * SMAX * 3 * DMODEL]; // QKV (half)
__device__ __half g_oh  [BATCH * SMAX * DMODEL];     // attention output (half)
__device__ float  g_o   [BATCH * SMAX * DMODEL];     // patch-embed GEMM output (fp32)
__device__ __half g_mlph[BATCH * SMAX * MLPD];       // patchify / GELU output (half)
__device__ float  g_p   [BATCH * NHEAD * PSTRIDE * PSTRIDE];
__device__ float  g_feat[BATCH * DMODEL];
__device__ float  g_score[BATCH * POOL];
__device__ float  g_lognorm[POOL];
__device__ float  g_logwn[POOL];
__device__ int    g_topk[BATCH * SEL];

// fp16, TRANSPOSED ([N][K] K-major) weight copies, built once per launch
__device__ __half g_wq [NLAYER * DMODEL * 3 * DMODEL];
__device__ __half g_wp [NLAYER * DMODEL * DMODEL];
__device__ __half g_w1 [NLAYER * DMODEL * MLPD];
__device__ __half g_w2 [NLAYER * MLPD * DMODEL];
__device__ __half g_wpc[DMODEL * DMODEL];

// ---------------- reductions (blockDim == 256 assumed) ----------------
__device__ __forceinline__ float block_sum256(float v, float* red) {
    int lane = threadIdx.x & 31, wid = threadIdx.x >> 5;
    #pragma unroll
    for (int o = 16; o; o >>= 1) v += __shfl_xor_sync(0xffffffffu, v, o);
    if (lane == 0) red[wid] = v;
    __syncthreads();
    float r = (lane < 8) ? red[lane] : 0.f;
    #pragma unroll
    for (int o = 4; o; o >>= 1) r += __shfl_xor_sync(0xffffffffu, r, o);
    r = __shfl_sync(0xffffffffu, r, 0);
    __syncthreads();
    return r;
}

// ---------------- mma / cp.async / ldmatrix helpers ----------------
__device__ __forceinline__ void mma_f16(float* c, const uint32_t* a, uint32_t b0, uint32_t b1) {
    asm volatile(
        "mma.sync.aligned.m16n8k16.row.col.f32.f16.f16.f32 "
        "{%0,%1,%2,%3}, {%4,%5,%6,%7}, {%8,%9}, {%0,%1,%2,%3};"
        : "+f"(c[0]), "+f"(c[1]), "+f"(c[2]), "+f"(c[3])
        : "r"(a[0]), "r"(a[1]), "r"(a[2]), "r"(a[3]), "r"(b0), "r"(b1));
}

__device__ __forceinline__ void ldsm_x4(uint32_t& r0, uint32_t& r1, uint32_t& r2, uint32_t& r3,
                                        uint32_t addr) {
    asm volatile("ldmatrix.sync.aligned.m8n8.x4.shared.b16 {%0,%1,%2,%3}, [%4];"
                 : "=r"(r0), "=r"(r1), "=r"(r2), "=r"(r3) : "r"(addr));
}

__device__ __forceinline__ void cp_async16(void* smem_dst, const void* gsrc, int src_bytes) {
    unsigned sa = (unsigned)__cvta_generic_to_shared(smem_dst);
    asm volatile("cp.async.cg.shared.global [%0], [%1], 16, %2;"
                 :: "r"(sa), "l"(gsrc), "r"(src_bytes));
}
__device__ __forceinline__ void cp_commit() {
    asm volatile("cp.async.commit_group;");
}

// unpack 8 halves (uint4) to floats
__device__ __forceinline__ void h8_to_f(const uint4& raw, float* f) {
    const __half2* hp = reinterpret_cast<const __half2*>(&raw);
    #pragma unroll
    for (int j = 0; j < 4; j++) {
        float2 t = __half22float2(hp[j]);
        f[j * 2] = t.x; f[j * 2 + 1] = t.y;
    }
}

// ---------------- weight transpose + fp16 round: dst[n*K+k] = h(src[k*N+n]) -------
__global__ void transpose_h_kernel(const float* __restrict__ src, __half* __restrict__ dst,
                                   int K, int N)
{
    __shared__ float tile[32][33];
    int l = blockIdx.z;
    const float* s = src + (size_t)l * K * N;
    __half* d = dst + (size_t)l * K * N;
    int k0 = blockIdx.y * 32, n0 = blockIdx.x * 32;
    for (int i = threadIdx.y; i < 32; i += 8)
        tile[i][threadIdx.x] = s[(size_t)(k0 + i) * N + n0 + threadIdx.x];
    __syncthreads();
    for (int i = threadIdx.y; i < 32; i += 8)
        d[(size_t)(n0 + i) * K + k0 + threadIdx.x] = __float2half_rn(tile[threadIdx.x][i]);
}

// ---------------- pipelined fp16 tensor-core GEMM (ldmatrix, TBK=64, 2 CTA/SM) -----
// C[M,N] = A[M,K] @ WT[N,K]^T + bias.  A, WT fp16; accumulate fp32.
// mode 0: store fp32; 1: GELU -> HALF; 2: += fp32; 3: store HALF.
#define TBM 128
#define TBN 128
#define TBK 64
#define HPITCH 72
#define GEMM_SMEM (4 * TBM * HPITCH * 2)   // 73728 B

__global__ void __launch_bounds__(256, 2) hgemm_kernel(
    const __half* __restrict__ A, const __half* __restrict__ WT,
    const float* __restrict__ bias, void* __restrict__ Cv,
    int M, int N, int K, int mode)
{
    extern __shared__ __half hsm[];
    __half* As = hsm;
    __half* Ws = hsm + 2 * TBM * HPITCH;

    int tid  = threadIdx.x;
    int warp = tid >> 5, lane = tid & 31;
    int g = lane >> 2, tig = lane & 3;
    int wm = (warp & 1) * 64;
    int wn = (warp >> 1) * 32;
    int row0 = blockIdx.y * TBM;
    int col0 = blockIdx.x * TBN;

    uint32_t a_off = (uint32_t)(((lane & 15) * HPITCH + (lane >> 4) * 8) * 2);
    uint32_t b_off = (uint32_t)((((lane & 7) + ((lane >> 4) & 1) * 8) * HPITCH + ((lane >> 3) & 1) * 8) * 2);

    float acc[4][4][4];
    #pragma unroll
    for (int mt = 0; mt < 4; mt++)
        #pragma unroll
        for (int nt = 0; nt < 4; nt++)
            #pragma unroll
            for (int i = 0; i < 4; i++) acc[mt][nt][i] = 0.f;

    auto load_tiles = [&](int k0, int buf) {
        __half* Ab = As + buf * TBM * HPITCH;
        __half* Wb = Ws + buf * TBN * HPITCH;
        #pragma unroll
        for (int i = 0; i < 4; i++) {
            int slot = tid + i * 256;
            int r = slot >> 3, c = slot & 7;
            int gm = row0 + r;
            const __half* src = A + (size_t)gm * K + k0 + c * 8;
            cp_async16(&Ab[r * HPITCH + c * 8], src, (gm < M) ? 16 : 0);
        }
        #pragma unroll
        for (int i = 0; i < 4; i++) {
            int slot = tid + i * 256;
            int n = slot >> 3, c = slot & 7;
            const __half* src = WT + (size_t)(col0 + n) * K + k0 + c * 8;
            cp_async16(&Wb[n * HPITCH + c * 8], src, 16);
        }
        cp_commit();
    };

    int T = K / TBK;
    load_tiles(0, 0);

    for (int t = 0; t < T; t++) {
        int buf = t & 1;
        if (t + 1 < T) {
            load_tiles((t + 1) * TBK, (t + 1) & 1);
            asm volatile("cp.async.wait_group 1;");
        } else {
            asm volatile("cp.async.wait_group 0;");
        }
        __syncthreads();

        uint32_t abase = (uint32_t)__cvta_generic_to_shared(As + buf * TBM * HPITCH);
        uint32_t bbase = (uint32_t)__cvta_generic_to_shared(Ws + buf * TBN * HPITCH);
        #pragma unroll
        for (int ks = 0; ks < 4; ks++) {
            int kk = ks * 16;
            uint32_t af[4][4];
            #pragma unroll
            for (int mt = 0; mt < 4; mt++) {
                uint32_t addr = abase + (uint32_t)(((wm + mt * 16) * HPITCH + kk) * 2) + a_off;
                ldsm_x4(af[mt][0], af[mt][1], af[mt][2], af[mt][3], addr);
            }
            uint32_t b0[4], b1[4];
            #pragma unroll
            for (int p = 0; p < 2; p++) {
                uint32_t addr = bbase + (uint32_t)(((wn + p * 16) * HPITCH + kk) * 2) + b_off;
                ldsm_x4(b0[p * 2], b1[p * 2], b0[p * 2 + 1], b1[p * 2 + 1], addr);
            }
            #pragma unroll
            for (int nt = 0; nt < 4; nt++)
                #pragma unroll
                for (int mt = 0; mt < 4; mt++)
                    mma_f16(acc[mt][nt], af[mt], b0[nt], b1[nt]);
        }
        __syncthreads();
    }

    float* Cf = (float*)Cv;
    __half* Ch = (__half*)Cv;
    #pragma unroll
    for (int mt = 0; mt < 4; mt++) {
        #pragma unroll
        for (int nt = 0; nt < 4; nt++) {
            int gn = col0 + wn + nt * 8 + tig * 2;
            #pragma unroll
            for (int half_ = 0; half_ < 2; half_++) {
                int gm = row0 + wm + mt * 16 + g + half_ * 8;
                if (gm >= M) continue;
                #pragma unroll
                for (int cc = 0; cc < 2; cc++) {
                    float v = acc[mt][nt][half_ * 2 + cc] + bias[gn + cc];
                    size_t off = (size_t)gm * N + gn + cc;
                    if (mode == 1) {
                        v = 0.5f * v * (1.0f + erff(v * 0.70710678118654752f));
                        Ch[off] = __float2half_rn(v);
                    } else if (mode == 2) {
                        Cf[off] += v;
                    } else if (mode == 3) {
                        Ch[off] = __float2half_rn(v);
                    } else {
                        Cf[off] = v;
                    }
                }
            }
        }
    }
}

// ---------------- LayerNorm over 768 ----------------
__global__ void ln_h_kernel(const float* __restrict__ in, __half* __restrict__ out,
                            const float* __restrict__ w, const float* __restrict__ b)
{
    __shared__ float red[8];
    const float* x = in + (long long)blockIdx.x * DMODEL;
    __half* y = out + (long long)blockIdx.x * DMODEL;
    int t = threadIdx.x;
    float v0 = x[t], v1 = x[t + 256], v2 = x[t + 512];
    float mean = block_sum256(v0 + v1 + v2, red) * (1.f / 768.f);
    float d0 = v0 - mean, d1 = v1 - mean, d2 = v2 - mean;
    float var = block_sum256(d0 * d0 + d1 * d1 + d2 * d2, red) * (1.f / 768.f);
    float rstd = rsqrtf(var + 1e-6f);
    y[t]       = __float2half_rn(d0 * rstd * w[t]       + b[t]);
    y[t + 256] = __float2half_rn(d1 * rstd * w[t + 256] + b[t + 256]);
    y[t + 512] = __float2half_rn(d2 * rstd * w[t + 512] + b[t + 512]);
}

__global__ void ln_f_kernel(const float* __restrict__ in, float* __restrict__ out,
                            const float* __restrict__ w, const float* __restrict__ b,
                            long long in_stride, long long out_stride)
{
    __shared__ float red[8];
    const float* x = in + (long long)blockIdx.x * in_stride;
    float* y = out + (long long)blockIdx.x * out_stride;
    int t = threadIdx.x;
    float v0 = x[t], v1 = x[t + 256], v2 = x[t + 512];
    float mean = block_sum256(v0 + v1 + v2, red) * (1.f / 768.f);
    float d0 = v0 - mean, d1 = v1 - mean, d2 = v2 - mean;
    float var = block_sum256(d0 * d0 + d1 * d1 + d2 * d2, red) * (1.f / 768.f);
    float rstd = rsqrtf(var + 1e-6f);
    y[t]       = d0 * rstd * w[t]       + b[t];
    y[t + 256] = d1 * rstd * w[t + 256] + b[t + 256];
    y[t + 512] = d2 * rstd * w[t + 512] + b[t + 512];
}

// ---------------- attention: fused score+softmax, then pv (QKV in half) ----------
#define SPAD 68
#define SROWP 228
#define SCORE_SMEM ((32 * SPAD + 64 * SPAD + 32 * SROWP) * 4)   // 55296 B

__global__ void __launch_bounds__(256) score_softmax_kernel(const __half* __restrict__ qkv, int S)
{
    extern __shared__ float sm[];
    float* Qs   = sm;
    float* KsT  = sm + 32 * SPAD;
    float* Srow = sm + 32 * SPAD + 64 * SPAD;

    int q0 = blockIdx.x * 32, h = blockIdx.y, b = blockIdx.z;
    int tid = threadIdx.x;
    int q = tid >> 3, kg = tid & 7;
    const __half* base = qkv + (size_t)b * S * (3 * DMODEL) + h * HDIM;
    float* prow = g_p + (((size_t)b * NHEAD + h) * PSTRIDE) * PSTRIDE;

    for (int i = tid; i < 32 * SROWP; i += 256) Srow[i] = -1e30f;

    // load Q tile [32 x 64]: 256 chunks of 8 halves
    {
        int r = tid >> 3, c8 = (tid & 7) * 8;
        int gq = q0 + r;
        float f[8] = {0, 0, 0, 0, 0, 0, 0, 0};
        if (gq < S) {
            uint4 raw = *reinterpret_cast<const uint4*>(&base[(size_t)gq * (3 * DMODEL) + c8]);
            h8_to_f(raw, f);
        }
        #pragma unroll
        for (int j = 0; j < 8; j++) Qs[r * SPAD + c8 + j] = f[j];
    }

    int ntile = (S + 63) >> 6;
    for (int kt = 0; kt < ntile; kt++) {
        int k0 = kt * 64;
        // K tile [64 x 64] -> KsT[d][k]; 512 chunks
        #pragma unroll
        for (int i = 0; i < 2; i++) {
            int slot = tid + i * 256;
            int r = slot >> 3, c8 = (slot & 7) * 8;
            int gk = k0 + r;
            float f[8] = {0, 0, 0, 0, 0, 0, 0, 0};
            if (gk < S) {
                uint4 raw = *reinterpret_cast<const uint4*>(&base[(size_t)gk * (3 * DMODEL) + DMODEL + c8]);
                h8_to_f(raw, f);
            }
            #pragma unroll
            for (int j = 0; j < 8; j++) KsT[(c8 + j) * SPAD + r] = f[j];
        }
        __syncthreads();

        float acc[8];
        #pragma unroll
        for (int j = 0; j < 8; j++) acc[j] = 0.f;
        #pragma unroll
        for (int d = 0; d < HDIM; d++) {
            float qa = Qs[q * SPAD + d];
            float4 kv0 = *reinterpret_cast<const float4*>(&KsT[d * SPAD + kg * 8]);
            float4 kv1 = *reinterpret_cast<const float4*>(&KsT[d * SPAD + kg * 8 + 4]);
            acc[0] += qa * kv0.x; acc[1] += qa * kv0.y;
            acc[2] += qa * kv0.z; acc[3] += qa * kv0.w;
            acc[4] += qa * kv1.x; acc[5] += qa * kv1.y;
            acc[6] += qa * kv1.z; acc[7] += qa * kv1.w;
        }
        #pragma unroll
        for (int j = 0; j < 8; j++) {
            int gk = k0 + kg * 8 + j;
            if (gk < S) Srow[q * SROWP + gk] = acc[j] * 0.125f;
        }
        __syncthreads();
    }

    float vals[28];
    float mx = -1e30f;
    #pragma unroll
    for (int i = 0; i < 28; i++) {
        vals[i] = Srow[q * SROWP + kg + i * 8];
        mx = fmaxf(mx, vals[i]);
    }
    #pragma unroll
    for (int o = 4; o; o >>= 1) mx = fmaxf(mx, __shfl_xor_sync(0xffffffffu, mx, o, 8));
    float sum = 0.f;
    #pragma unroll
    for (int i = 0; i < 28; i++) { vals[i] = expf(vals[i] - mx); sum += vals[i]; }
    #pragma unroll
    for (int o = 4; o; o >>= 1) sum += __shfl_xor_sync(0xffffffffu, sum, o, 8);
    float inv = 1.f / sum;

    int gq = q0 + q;
    if (gq < S) {
        float* pr = prow + (size_t)gq * PSTRIDE;
        #pragma unroll
        for (int i = 0; i < 28; i++) pr[kg + i * 8] = vals[i] * inv;
    }
}

__global__ void __launch_bounds__(256) pv_kernel(const __half* __restrict__ qkv,
                                                 __half* __restrict__ o, int S)
{
    __shared__ float Ps[32][SPAD];
    __shared__ float Vs[64][SPAD];
    int q0 = blockIdx.x * 32, h = blockIdx.y, b = blockIdx.z;
    int tid = threadIdx.x;
    int q = tid >> 3, dg = tid & 7;
    const __half* vbase = qkv + (size_t)b * S * (3 * DMODEL) + 2 * DMODEL + h * HDIM;
    const float* prow = g_p + (((size_t)b * NHEAD + h) * PSTRIDE) * PSTRIDE;

    float acc[8];
    #pragma unroll
    for (int j = 0; j < 8; j++) acc[j] = 0.f;

    int ntile = (S + 63) >> 6;
    for (int kt = 0; kt < ntile; kt++) {
        int k0 = kt * 64;
        #pragma unroll
        for (int i = 0; i < 2; i++) {
            int slot = tid + i * 256;
            int r = slot >> 4, c4 = (slot & 15) * 4;
            int gq = q0 + r;
            float4 v = make_float4(0.f, 0.f, 0.f, 0.f);
            if (gq < S) {
                #pragma unroll
                for (int c = 0; c < 4; c++) {
                    int gk = k0 + c4 + c;
                    ((float*)&v)[c] = (gk < S) ? prow[(size_t)gq * PSTRIDE + gk] : 0.f;
                }
            }
            *reinterpret_cast<float4*>(&Ps[r][c4]) = v;
        }
        #pragma unroll
        for (int i = 0; i < 2; i++) {
            int slot = tid + i * 256;
            int r = slot >> 3, c8 = (slot & 7) * 8;
            int gk = k0 + r;
            float f[8] = {0, 0, 0, 0, 0, 0, 0, 0};
            if (gk < S) {
                uint4 raw = *reinterpret_cast<const uint4*>(&vbase[(size_t)gk * (3 * DMODEL) + c8]);
                h8_to_f(raw, f);
            }
            #pragma unroll
            for (int j = 0; j < 8; j++) Vs[r][c8 + j] = f[j];
        }
        __syncthreads();

        #pragma unroll
        for (int k = 0; k < 64; k++) {
            float p = Ps[q][k];
            float4 v0 = *reinterpret_cast<const float4*>(&Vs[k][dg * 8]);
            float4 v1 = *reinterpret_cast<const float4*>(&Vs[k][dg * 8 + 4]);
            acc[0] += p * v0.x; acc[1] += p * v0.y;
            acc[2] += p * v0.z; acc[3] += p * v0.w;
            acc[4] += p * v1.x; acc[5] += p * v1.y;
            acc[6] += p * v1.z; acc[7] += p * v1.w;
        }
        __syncthreads();
    }

    int gq = q0 + q;
    if (gq < S) {
        __half* ow = o + ((size_t)(b * S + gq)) * DMODEL + h * HDIM + dg * 8;
        #pragma unroll
        for (int j = 0; j < 8; j++) ow[j] = __float2half_rn(acc[j]);
    }
}

// ---------------- patchify + embedding ----------------
__global__ void patchify_kernel(const float* __restrict__ in)
{
    size_t i = (size_t)blockIdx.x * 256 + threadIdx.x;
    if (i >= (size_t)BATCH * 196 * DMODEL) return;
    int v = (int)(i % DMODEL);
    size_t t = i / DMODEL;
    int p = (int)(t % 196);
    int b = (int)(t / 196);
    int c = v >> 8;
    int py = (v & 255) >> 4;
    int px = v & 15;
    int gy = p / 14, gx = p % 14;
    g_mlph[i] = __float2half_rn(in[(((size_t)b * 3 + c) * 224 + gy * 16 + py) * 224 + gx * 16 + px]);
}

__global__ void embed_kernel(const float* __restrict__ cls, const float* __restrict__ pos)
{
    size_t i = (size_t)blockIdx.x * 256 + threadIdx.x;
    if (i >= (size_t)BATCH * S1 * DMODEL) return;
    int d = (int)(i % DMODEL);
    size_t t = i / DMODEL;
    int s = (int)(t % S1);
    int b = (int)(t / S1);
    float v;
    if (s == 0) v = cls[d] + pos[d];
    else        v = g_o[((size_t)b * 196 + (s - 1)) * DMODEL + d] + pos[(size_t)s * DMODEL + d];
    g_x[i] = v;
    g_x0[i] = v;
}

// ---------------- routing ----------------
__global__ void pool_stats_kernel(const float* __restrict__ var)
{
    __shared__ float red[8];
    int p = blockIdx.x;
    const float* v = var + (size_t)p * DMODEL * DMODEL;
    float s = 0.f;
    for (int i = threadIdx.x; i < DMODEL * DMODEL; i += 256) { float t = v[i]; s += t * t; }
    float tot = block_sum256(s, red);
    if (threadIdx.x == 0) g_lognorm[p] = 0.25f * logf(tot);
}

__global__ void logwn_kernel(const float* __restrict__ freq)
{
    float m = freq[0];
    for (int i = 1; i < POOL; i++) m = fmaxf(m, freq[i]);
    float w[POOL]; float ss = 0.f;
    for (int i = 0; i < POOL; i++) { w[i] = m - freq[i]; ss += w[i] * w[i]; }
    float nz = fmaxf(sqrtf(ss), 1e-12f);
    for (int i = 0; i < POOL; i++) g_logwn[i] = logf(fmaxf(w[i] / nz, 1e-30f));
}

__global__ void quad_kernel(const float* __restrict__ keys, const float* __restrict__ inv_var)
{
    __shared__ float diff[DMODEL];
    __shared__ float red[8];
    int b = blockIdx.x, p = blockIdx.y;
    for (int i = threadIdx.x; i < DMODEL; i += 256)
        diff[i] = g_feat[b * DMODEL + i] - keys[p * DMODEL + i];
    __syncthreads();
    const float* M = inv_var + (size_t)p * DMODEL * DMODEL;
    float acc = 0.f;
    #pragma unroll
    for (int ei = 0; ei < 3; ei++) {
        int e = threadIdx.x + ei * 256;
        float inner = 0.f;
        for (int d = 0; d < DMODEL; d++)
            inner += diff[d] * M[(size_t)d * DMODEL + e];
        acc += inner * diff[e];
    }
    float quad = block_sum256(acc, red);
    if (threadIdx.x == 0)
        g_score[b * POOL + p] = -0.5f * quad + g_lognorm[p] + g_logwn[p];
}

__global__ void topk_kernel()
{
    int b = threadIdx.x;
    if (b >= BATCH) return;
    float s[POOL]; bool used[POOL];
    for (int p = 0; p < POOL; p++) { s[p] = g_score[b * POOL + p]; used[p] = false; }
    for (int i = 0; i < SEL; i++) {
        int best = 0; float bv = 3.0e38f;
        for (int p = 0; p < POOL; p++)
            if (!used[p] && s[p] < bv) { bv = s[p]; best = p; }
        used[best] = true;
        g_topk[b * SEL + i] = best;
    }
}

__global__ void build_sx_kernel(const float* __restrict__ prompts, const float* __restrict__ pos)
{
    size_t i = (size_t)blockIdx.x * 256 + threadIdx.x;
    if (i >= (size_t)BATCH * SMAX * DMODEL) return;
    int d = (int)(i % DMODEL);
    size_t t = i / DMODEL;
    int s = (int)(t % SMAX);
    int b = (int)(t / SMAX);
    float v;
    if (s == 0) {
        v = g_x0[(size_t)b * S1 * DMODEL + d];
    } else if (s <= SEL * PLEN) {
        int idx = s - 1;
        int pi = idx / PLEN, j = idx % PLEN;
        int pool = g_topk[b * SEL + pi];
        v = prompts[((size_t)pool * PLEN + j) * DMODEL + d] + pos[d];
    } else {
        v = g_x0[((size_t)b * S1 + (s - SEL * PLEN)) * DMODEL + d];
    }
    g_x[i] = v;
}

// ---------------- epilogue ----------------
__global__ void feat_kernel()
{
    int i = blockIdx.x * 256 + threadIdx.x;
    if (i >= BATCH * DMODEL) return;
    int b = i / DMODEL, d = i % DMODEL;
    float s = 0.f;
    for (int t = 1; t <= SEL * PLEN; t++)
        s += g_h[((size_t)b * SMAX + t) * DMODEL + d];
    g_feat[i] = s * (1.f / (SEL * PLEN));
}

__global__ void head_kernel(const float* __restrict__ hw, const float* __restrict__ hb,
                            float* __restrict__ out)
{
    int i = blockIdx.x * 256 + threadIdx.x;
    if (i >= BATCH * NCLS) return;
    int b = i / NCLS, n = i % NCLS;
    float acc = hb[n];
    for (int k = 0; k < DMODEL; k++) acc += g_feat[b * DMODEL + k] * hw[k * NCLS + n];
    out[i] = acc;
}

// ---------------- host orchestration ----------------
static void run_vit(int S, int M,
    const float* ln1w, const float* ln1b, const __half* qkvw, const float* qkvb,
    const __half* pw, const float* pb, const float* ln2w, const float* ln2b,
    const __half* f1w, const float* f1b, const __half* f2w, const float* f2b,
    float* px, __half* phh, __half* pqkvh, __half* poh, __half* pmlph)
{
    int gy = (M + TBM - 1) / TBM;
    int qt = (S + 31) / 32;
    for (int l = 0; l < NLAYER; l++) {
        ln_h_kernel<<<M, 256>>>(px, phh, ln1w + (size_t)l * DMODEL, ln1b + (size_t)l * DMODEL);
        hgemm_kernel<<<dim3(3 * DMODEL / TBN, gy), 256, GEMM_SMEM>>>(phh, qkvw + (size_t)l * DMODEL * 3 * DMODEL,
                                                          qkvb + (size_t)l * 3 * DMODEL, pqkvh, M, 3 * DMODEL, DMODEL, 3);
        score_softmax_kernel<<<dim3(qt, NHEAD, BATCH), 256, SCORE_SMEM>>>(pqkvh, S);
        pv_kernel<<<dim3(qt, NHEAD, BATCH), 256>>>(pqkvh, poh, S);
        hgemm_kernel<<<dim3(DMODEL / TBN, gy), 256, GEMM_SMEM>>>(poh, pw + (size_t)l * DMODEL * DMODEL,
                                                      pb + (size_t)l * DMODEL, px, M, DMODEL, DMODEL, 2);
        ln_h_kernel<<<M, 256>>>(px, phh, ln2w + (size_t)l * DMODEL, ln2b + (size_t)l * DMODEL);
        hgemm_kernel<<<dim3(MLPD / TBN, gy), 256, GEMM_SMEM>>>(phh, f1w + (size_t)l * DMODEL * MLPD,
                                                    f1b + (size_t)l * MLPD, pmlph, M, MLPD, DMODEL, 1);
        hgemm_kernel<<<dim3(DMODEL / TBN, gy), 256, GEMM_SMEM>>>(pmlph, f2w + (size_t)l * MLPD * DMODEL,
                                                      f2b + (size_t)l * DMODEL, px, M, DMODEL, MLPD, 2);
    }
}

extern "C" void kernel_launch(void* const* d_in, const int* in_sizes, int n_in,
                              void* d_out, int out_size)
{
    const float* inputs    = (const float*)d_in[0];
    const float* patch_w   = (const float*)d_in[1];
    const float* patch_b   = (const float*)d_in[2];
    const float* cls_token = (const float*)d_in[3];
    const float* pos_embed = (const float*)d_in[4];
    const float* ln1_w = (const float*)d_in[5];
    const float* ln1_b = (const float*)d_in[6];
    const float* qkv_w = (const float*)d_in[7];
    const float* qkv_b = (const float*)d_in[8];
    const float* proj_w = (const float*)d_in[9];
    const float* proj_b = (const float*)d_in[10];
    const float* ln2_w = (const float*)d_in[11];
    const float* ln2_b = (const float*)d_in[12];
    const float* fc1_w = (const float*)d_in[13];
    const float* fc1_b = (const float*)d_in[14];
    const float* fc2_w = (const float*)d_in[15];
    const float* fc2_b = (const float*)d_in[16];
    const float* norm_w = (const float*)d_in[17];
    const float* norm_b = (const float*)d_in[18];
    const float* head_w = (const float*)d_in[19];
    const float* head_b = (const float*)d_in[20];
    const float* key_pool = (const float*)d_in[21];
    const float* frequency = (const float*)d_in[22];
    const float* prompts = (const float*)d_in[23];
    const float* variance = (const float*)d_in[24];
    const float* inv_variance = (const float*)d_in[25];

    static bool attr_set = false;
    if (!attr_set) {
        cudaFuncSetAttribute(hgemm_kernel, cudaFuncAttributeMaxDynamicSharedMemorySize, GEMM_SMEM);
        cudaFuncSetAttribute(score_softmax_kernel, cudaFuncAttributeMaxDynamicSharedMemorySize, SCORE_SMEM);
        attr_set = true;
    }

    float *px, *ph, *po, *pfeat;
    __half *phh, *pqkvh, *poh, *pmlph;
    __half *pwq, *pwp, *pw1, *pw2, *pwpc;
    cudaGetSymbolAddress((void**)&px,    g_x);
    cudaGetSymbolAddress((void**)&ph,    g_h);
    cudaGetSymbolAddress((void**)&phh,   g_hh);
    cudaGetSymbolAddress((void**)&pqkvh, g_qkvh);
    cudaGetSymbolAddress((void**)&po,    g_o);
    cudaGetSymbolAddress((void**)&poh,   g_oh);
    cudaGetSymbolAddress((void**)&pmlph, g_mlph);
    cudaGetSymbolAddress((void**)&pfeat, g_feat);
    cudaGetSymbolAddress((void**)&pwq,   g_wq);
    cudaGetSymbolAddress((void**)&pwp,   g_wp);
    cudaGetSymbolAddress((void**)&pw1,   g_w1);
    cudaGetSymbolAddress((void**)&pw2,   g_w2);
    cudaGetSymbolAddress((void**)&pwpc,  g_wpc);

    // 0) weight prep: transpose to [N][K] + fp16 round (once per launch)
    {
        dim3 blk(32, 8);
        transpose_h_kernel<<<dim3(3 * DMODEL / 32, DMODEL / 32, NLAYER), blk>>>(qkv_w, pwq, DMODEL, 3 * DMODEL);
        transpose_h_kernel<<<dim3(DMODEL / 32, DMODEL / 32, NLAYER), blk>>>(proj_w, pwp, DMODEL, DMODEL);
        transpose_h_kernel<<<dim3(MLPD / 32, DMODEL / 32, NLAYER), blk>>>(fc1_w, pw1, DMODEL, MLPD);
        transpose_h_kernel<<<dim3(DMODEL / 32, MLPD / 32, NLAYER), blk>>>(fc2_w, pw2, MLPD, DMODEL);
        transpose_h_kernel<<<dim3(DMODEL / 32, DMODEL / 32, 1), blk>>>(patch_w, pwpc, DMODEL, DMODEL);
    }

    // 1) patch embed
    patchify_kernel<<<(BATCH * 196 * DMODEL + 255) / 256, 256>>>(inputs);
    hgemm_kernel<<<dim3(DMODEL / TBN, (BATCH * 196 + TBM - 1) / TBM), 256, GEMM_SMEM>>>(
        pmlph, pwpc, patch_b, po, BATCH * 196, DMODEL, DMODEL, 0);
    embed_kernel<<<(BATCH * S1 * DMODEL + 255) / 256, 256>>>(cls_token, pos_embed);

    // 2) first ViT pass (S=197)
    run_vit(S1, BATCH * S1, ln1_w, ln1_b, pwq, qkv_b, pwp, proj_b,
            ln2_w, ln2_b, pw1, fc1_b, pw2, fc2_b, px, phh, pqkvh, poh, pmlph);

    // 3) routing
    ln_f_kernel<<<BATCH, 256>>>(px, pfeat, norm_w, norm_b, (long long)S1 * DMODEL, DMODEL);
    pool_stats_kernel<<<POOL, 256>>>(variance);
    logwn_kernel<<<1, 1>>>(frequency);
    quad_kernel<<<dim3(BATCH, POOL), 256>>>(key_pool, inv_variance);
    topk_kernel<<<1, 32>>>();

    // 4) splice prompts (S=222)
    build_sx_kernel<<<(BATCH * SMAX * DMODEL + 255) / 256, 256>>>(prompts, pos_embed);

    // 5) second ViT pass (S=222)
    run_vit(SMAX, BATCH * SMAX, ln1_w, ln1_b, pwq, qkv_b, pwp, proj_b,
            ln2_w, ln2_b, pw1, fc1_b, pw2, fc2_b, px, phh, pqkvh, poh, pmlph);

    // 6) final LN, mean over prompt tokens, head
    ln_f_kernel<<<BATCH * SMAX, 256>>>(px, ph, norm_w, norm_b, DMODEL, DMODEL);
    feat_kernel<<<(BATCH * DMODEL + 255) / 256, 256>>>();
    head_kernel<<<(BATCH * NCLS + 255) / 256, 256>>>(head_w, head_b, (float*)d_out);
}